// round 9
// baseline (speedup 1.0000x reference)
#include <cuda_runtime.h>
#include <cuda_bf16.h>
#include <math.h>

#define BB 128
#define TT 256
#define HH 768
#define KK 64

typedef unsigned long long u64t;

// ---- packed f32x2 helpers ------------------------------------------------
__device__ __forceinline__ u64t ffma2(u64t a, u64t b, u64t c) {
    u64t d;
    asm("fma.rn.f32x2 %0, %1, %2, %3;" : "=l"(d) : "l"(a), "l"(b), "l"(c));
    return d;
}
__device__ __forceinline__ u64t pack2(float lo, float hi) {
    u64t d;
    unsigned a = __float_as_uint(lo), b = __float_as_uint(hi);
    asm("mov.b64 %0, {%1, %2};" : "=l"(d) : "r"(a), "r"(b));
    return d;
}
__device__ __forceinline__ void unpack2(u64t v, float* lo, float* hi) {
    unsigned a, b;
    asm("mov.b64 {%0, %1}, %2;" : "=r"(a), "=r"(b) : "l"(v));
    *lo = __uint_as_float(a);
    *hi = __uint_as_float(b);
}
__device__ __forceinline__ unsigned smem_u32(const void* p) {
    unsigned a;
    asm("{ .reg .u64 t; cvta.to.shared.u64 t, %1; cvt.u32.u64 %0, t; }"
        : "=r"(a) : "l"(p));
    return a;
}
__device__ __forceinline__ int ld_acquire_sh(unsigned a) {
    int v;
    asm volatile("ld.acquire.cta.shared.b32 %0, [%1];" : "=r"(v) : "r"(a) : "memory");
    return v;
}
__device__ __forceinline__ void st_release_sh(unsigned a, int v) {
    asm volatile("st.release.cta.shared.b32 [%0], %1;" :: "r"(a), "r"(v) : "memory");
}

// Smem layout (bytes)
#define OFF_EMIS   0                         // 256*64*4   = 65536
#define OFF_AS     65536                     // 16*32*4    = 2048
#define OFF_BS2    67584                     // 16*64*8    = 8192
#define OFF_TT     75776                     // 64*68*4    = 17408
#define OFF_BP     93184                     // 255*64     = 16320
#define OFF_PATH   109504                    // 256*4      = 1024
#define OFF_V      110528                    // 3*64*4     = 768
#define OFF_P      111296                    // 2*64*4     = 512
#define OFF_RED    111808                    // 8*4        = 32
#define OFF_MISC   111840                    // len_v, len_f, flag
#define SMEM_BYTES 111872

// ---------------------------------------------------------------------------
// Fused kernel: per-batch GEMM producer + CRF consumers. grid=128, 384 thr:
//   warps 0-3  (tid 0..127):   Viterbi consumer      (bar.sync 1, 128)
//   warps 4-7  (tid 128..255): forward consumer      (bar.sync 2, 128)
//   warps 8-11 (tid 256..383): GEMM emission producer (bar.sync 3, 128)
// Producers fill s_emis in 32-row mini-tiles, publish via release-flag;
// consumers gate their 4-step prefetch on acquire-loads of the flag.
// ---------------------------------------------------------------------------
__global__ __launch_bounds__(384, 1) void fused_kernel(
    const float* __restrict__ hidden,
    const int* __restrict__ masks,
    const int* __restrict__ target,
    const float* __restrict__ Wm,
    const float* __restrict__ bias,
    const float* __restrict__ trans_g,
    float* __restrict__ out_dec,
    float* __restrict__ out_ll)
{
    extern __shared__ __align__(16) char smem[];
    float* s_emis = (float*)(smem + OFF_EMIS);
    float* s_As   = (float*)(smem + OFF_AS);
    u64t*  s_Bs2  = (u64t*)(smem + OFF_BS2);
    float* s_tt   = (float*)(smem + OFF_TT);
    unsigned char* s_bp = (unsigned char*)(smem + OFF_BP);
    int*   s_path = (int*)(smem + OFF_PATH);
    float* s_v    = (float*)(smem + OFF_V);
    float* s_P    = (float*)(smem + OFF_P);
    float* s_red  = (float*)(smem + OFF_RED);
    int*   s_misc = (int*)(smem + OFF_MISC);    // [0]=len_v [1]=len_f [2]=flag

    const int tid = threadIdx.x;
    const int b = blockIdx.x;
    const unsigned flag_a = smem_u32(&s_misc[2]);

    if (tid == 0) s_misc[2] = 0;
    __syncthreads();    // only block-wide barrier; groups diverge after this

    if (tid < 128) {
        // ================= VITERBI: 4 warps, 2 threads per state ============
        if (tid < 32) {
            int acc = 0;
#pragma unroll
            for (int i = 0; i < 8; i++) acc += masks[b * TT + tid + 32 * i];
#pragma unroll
            for (int o = 16; o; o >>= 1) acc += __shfl_xor_sync(0xFFFFFFFFu, acc, o);
            if (tid == 0) s_misc[0] = acc;
        }

        const int j = tid >> 1;
        const int h = tid & 1;
        const int k0 = h * 32;

        for (int i = tid; i < 4096; i += 128) {
            int k = i >> 6, jj = i & 63;
            s_tt[jj * 68 + k] = trans_g[i];
        }
        float Tcol[32];
#pragma unroll
        for (int kk = 0; kk < 32; kk++)
            Tcol[kk] = trans_g[(k0 + kk) * KK + j];

        // wait for first mini-tile (rows 0..31)
        while (ld_acquire_sh(flag_a) < 1) __nanosleep(64);

        float e0 = s_emis[j];
        float ecur[4];
#pragma unroll
        for (int i = 0; i < 4; i++) ecur[i] = s_emis[(1 + i) * KK + j];

        float prevV = e0;
        if (h == 0) s_v[0 * 64 + j] = e0;
        asm volatile("bar.sync 1, 128;" ::: "memory");
        const int len = s_misc[0];
        int rbuf = 0;

        float pqm[8];
        float pbv = 0.f;
        int pvalid = 0;
        int pt = 0;

        for (int tb = 1; tb < TT; tb += 4) {
            int hrow = tb + 7; if (hrow > 255) hrow = 255;
            int need = (hrow >> 5) + 1;
            while (ld_acquire_sh(flag_a) < need) __nanosleep(64);

            float enext[4];
#pragma unroll
            for (int i = 0; i < 4; i++) {
                int tt = tb + 4 + i;
                enext[i] = (tt < TT) ? s_emis[tt * KK + j] : 0.f;
            }
#pragma unroll
            for (int i = 0; i < 4; i++) {
                const int t = tb + i;
                if (t >= TT) break;

                const int wbuf = (rbuf == 2) ? 0 : rbuf + 1;
                const int obuf = (wbuf == 2) ? 0 : wbuf + 1;

                const float4* V4 = (const float4*)&s_v[rbuf * 64 + k0];
                float4 v0 = V4[0], v1 = V4[1], v2 = V4[2], v3 = V4[3];
                float4 v4 = V4[4], v5 = V4[5], v6 = V4[6], v7 = V4[7];

                if (pvalid) {
                    int li = 255;
                    if (pvalid == 1) {
                        int qq = 8;
#pragma unroll
                        for (int m = 7; m >= 0; m--)
                            qq = (pqm[m] == pbv) ? m : qq;
                        if (qq < 8) {
                            int kq = k0 + qq * 4;
                            float4 vq = *(const float4*)&s_v[obuf * 64 + kq];
                            float4 tq = *(const float4*)&s_tt[j * 68 + kq];
                            float c0 = vq.x + tq.x, c1 = vq.y + tq.y;
                            float c2 = vq.z + tq.z, c3 = vq.w + tq.w;
                            li = kq + 3;
                            li = (c2 == pbv) ? kq + 2 : li;
                            li = (c1 == pbv) ? kq + 1 : li;
                            li = (c0 == pbv) ? kq : li;
                        }
                        int oi = __shfl_xor_sync(0xFFFFFFFFu, li, 1);
                        li = min(li, oi);
                    } else {
                        li = j;
                    }
                    if (h == 0) s_bp[(pt - 1) * KK + j] = (unsigned char)li;
                }

                float qm[8];
                {
                    float c0, c1, c2, c3;
                    c0 = v0.x + Tcol[0];  c1 = v0.y + Tcol[1];
                    c2 = v0.z + Tcol[2];  c3 = v0.w + Tcol[3];
                    qm[0] = fmaxf(fmaxf(c0, c1), fmaxf(c2, c3));
                    c0 = v1.x + Tcol[4];  c1 = v1.y + Tcol[5];
                    c2 = v1.z + Tcol[6];  c3 = v1.w + Tcol[7];
                    qm[1] = fmaxf(fmaxf(c0, c1), fmaxf(c2, c3));
                    c0 = v2.x + Tcol[8];  c1 = v2.y + Tcol[9];
                    c2 = v2.z + Tcol[10]; c3 = v2.w + Tcol[11];
                    qm[2] = fmaxf(fmaxf(c0, c1), fmaxf(c2, c3));
                    c0 = v3.x + Tcol[12]; c1 = v3.y + Tcol[13];
                    c2 = v3.z + Tcol[14]; c3 = v3.w + Tcol[15];
                    qm[3] = fmaxf(fmaxf(c0, c1), fmaxf(c2, c3));
                    c0 = v4.x + Tcol[16]; c1 = v4.y + Tcol[17];
                    c2 = v4.z + Tcol[18]; c3 = v4.w + Tcol[19];
                    qm[4] = fmaxf(fmaxf(c0, c1), fmaxf(c2, c3));
                    c0 = v5.x + Tcol[20]; c1 = v5.y + Tcol[21];
                    c2 = v5.z + Tcol[22]; c3 = v5.w + Tcol[23];
                    qm[5] = fmaxf(fmaxf(c0, c1), fmaxf(c2, c3));
                    c0 = v6.x + Tcol[24]; c1 = v6.y + Tcol[25];
                    c2 = v6.z + Tcol[26]; c3 = v6.w + Tcol[27];
                    qm[6] = fmaxf(fmaxf(c0, c1), fmaxf(c2, c3));
                    c0 = v7.x + Tcol[28]; c1 = v7.y + Tcol[29];
                    c2 = v7.z + Tcol[30]; c3 = v7.w + Tcol[31];
                    qm[7] = fmaxf(fmaxf(c0, c1), fmaxf(c2, c3));
                }
                float m0 = fmaxf(qm[0], qm[1]), m1 = fmaxf(qm[2], qm[3]);
                float m2 = fmaxf(qm[4], qm[5]), m3 = fmaxf(qm[6], qm[7]);
                float bv = fmaxf(fmaxf(m0, m1), fmaxf(m2, m3));
                bv = fmaxf(bv, __shfl_xor_sync(0xFFFFFFFFu, bv, 1));

                float newv = (t < len) ? (bv + ecur[i]) : prevV;
                if (h == 0) s_v[wbuf * 64 + j] = newv;
                prevV = newv;

#pragma unroll
                for (int m = 0; m < 8; m++) pqm[m] = qm[m];
                pbv = bv;
                pvalid = (t < len) ? 1 : 2;
                pt = t;

                asm volatile("bar.sync 1, 128;" ::: "memory");
                rbuf = wbuf;
            }
#pragma unroll
            for (int i = 0; i < 4; i++) ecur[i] = enext[i];
        }

        {   // final pending bp (t = 255)
            const int obuf = (rbuf == 0) ? 2 : rbuf - 1;
            int li = 255;
            if (pvalid == 1) {
                int qq = 8;
#pragma unroll
                for (int m = 7; m >= 0; m--)
                    qq = (pqm[m] == pbv) ? m : qq;
                if (qq < 8) {
                    int kq = k0 + qq * 4;
                    float4 vq = *(const float4*)&s_v[obuf * 64 + kq];
                    float4 tq = *(const float4*)&s_tt[j * 68 + kq];
                    float c0 = vq.x + tq.x, c1 = vq.y + tq.y;
                    float c2 = vq.z + tq.z, c3 = vq.w + tq.w;
                    li = kq + 3;
                    li = (c2 == pbv) ? kq + 2 : li;
                    li = (c1 == pbv) ? kq + 1 : li;
                    li = (c0 == pbv) ? kq : li;
                }
                int oi = __shfl_xor_sync(0xFFFFFFFFu, li, 1);
                li = min(li, oi);
            } else {
                li = j;
            }
            if (h == 0) s_bp[(pt - 1) * KK + j] = (unsigned char)li;
        }
        asm volatile("bar.sync 1, 128;" ::: "memory");

        if (tid == 0) {
            float bvv = s_v[rbuf * 64 + 0];
            int tg = 0;
#pragma unroll
            for (int k = 1; k < KK; k++)
                if (s_v[rbuf * 64 + k] > bvv) { bvv = s_v[rbuf * 64 + k]; tg = k; }
            s_path[TT - 1] = tg;
            for (int t = TT - 1; t >= 1; t--) {
                tg = s_bp[(t - 1) * KK + tg];
                s_path[t - 1] = tg;
            }
        }
        asm volatile("bar.sync 1, 128;" ::: "memory");
#pragma unroll
        for (int i = 0; i < 2; i++) {
            int tt = tid + 128 * i;
            out_dec[(size_t)b * TT + tt] = (float)((tt < len) ? s_path[tt] : 0);
        }

    } else if (tid < 256) {
        // ============ FORWARD: 4 warps (tid 128..255), 2 threads/state ======
        const int ft = tid - 128;

        if (ft < 32) {
            int acc = 0;
#pragma unroll
            for (int i = 0; i < 8; i++) acc += masks[b * TT + ft + 32 * i];
#pragma unroll
            for (int o = 16; o; o >>= 1) acc += __shfl_xor_sync(0xFFFFFFFFu, acc, o);
            if (ft == 0) s_misc[1] = acc;
        }

        const int j = ft >> 1;
        const int h = ft & 1;
        const int k0 = h * 32;

        u64t E2[16];
#pragma unroll
        for (int m = 0; m < 16; m++) {
            float t0 = trans_g[(k0 + 2 * m) * KK + j];
            float t1 = trans_g[(k0 + 2 * m + 1) * KK + j];
            E2[m] = pack2(expf(t0), expf(t1));
        }

        while (ld_acquire_sh(flag_a) < 1) __nanosleep(64);

        float e0 = s_emis[j];
        float ecur[4];
#pragma unroll
        for (int i = 0; i < 4; i++) ecur[i] = s_emis[(1 + i) * KK + j];

        float prevP = __expf(e0);
        int iexp = 0;
        if (h == 0) s_P[0 * 64 + j] = prevP;
        asm volatile("bar.sync 2, 128;" ::: "memory");
        const int len = s_misc[1];
        int buf = 0;

        for (int tb = 1; tb < TT; tb += 4) {
            int hrow = tb + 7; if (hrow > 255) hrow = 255;
            int need = (hrow >> 5) + 1;
            while (ld_acquire_sh(flag_a) < need) __nanosleep(64);

            float enext[4];
#pragma unroll
            for (int i = 0; i < 4; i++) {
                int tt = tb + 4 + i;
                enext[i] = (tt < TT) ? s_emis[tt * KK + j] : 0.f;
            }
            float eexp[4];
#pragma unroll
            for (int i = 0; i < 4; i++) eexp[i] = __expf(ecur[i]);

#pragma unroll
            for (int i = 0; i < 4; i++) {
                const int t = tb + i;
                if (t >= TT) break;

                float p0 = s_P[buf * 64 + 0];
                const u64t* P2 = (const u64t*)&s_P[buf * 64 + k0];
                u64t s0 = 0ull, s1 = 0ull, s2 = 0ull, s3 = 0ull;
#pragma unroll
                for (int m = 0; m < 4; m++) {
                    s0 = ffma2(P2[4 * m + 0], E2[4 * m + 0], s0);
                    s1 = ffma2(P2[4 * m + 1], E2[4 * m + 1], s1);
                    s2 = ffma2(P2[4 * m + 2], E2[4 * m + 2], s2);
                    s3 = ffma2(P2[4 * m + 3], E2[4 * m + 3], s3);
                }
                float l0, h0, l1, h1, l2, h2, l3, h3;
                unpack2(s0, &l0, &h0);
                unpack2(s1, &l1, &h1);
                unpack2(s2, &l2, &h2);
                unpack2(s3, &l3, &h3);
                float S = ((l0 + h0) + (l1 + h1)) + ((l2 + h2) + (l3 + h3));
                S += __shfl_xor_sync(0xFFFFFFFFu, S, 1);

                int e0i = (int)(__float_as_uint(p0) >> 23);
                float scale = __uint_as_float((unsigned)(254 - e0i) << 23);
                if (t < len) {
                    prevP = S * scale * eexp[i];
                    iexp += e0i - 127;
                }
                if (h == 0) s_P[(buf ^ 1) * 64 + j] = prevP;
                asm volatile("bar.sync 2, 128;" ::: "memory");
                buf ^= 1;
            }
#pragma unroll
            for (int i = 0; i < 4; i++) ecur[i] = enext[i];
        }

        float sp = (h == 0) ? prevP : 0.f;
#pragma unroll
        for (int o = 16; o; o >>= 1) sp += __shfl_xor_sync(0xFFFFFFFFu, sp, o);
        if ((ft & 31) == 0) s_red[ft >> 5] = sp;

        float uacc = 0.f;
#pragma unroll
        for (int i = 0; i < 2; i++) {
            int tt = ft + 128 * i;
            if (tt < len) {
                int tg = target[b * TT + tt];
                uacc += s_emis[tt * KK + tg];
                if (tt >= 1) uacc += trans_g[target[b * TT + tt - 1] * KK + tg];
            }
        }
#pragma unroll
        for (int o = 16; o; o >>= 1) uacc += __shfl_xor_sync(0xFFFFFFFFu, uacc, o);
        if ((ft & 31) == 0) s_red[4 + (ft >> 5)] = uacc;
        asm volatile("bar.sync 2, 128;" ::: "memory");

        if (ft == 0) {
            float sumP = s_red[0] + s_red[1] + s_red[2] + s_red[3];
            float score = s_red[4] + s_red[5] + s_red[6] + s_red[7];
            const float LN2 = 0.69314718055994531f;
            out_ll[b] = score - ((float)iexp * LN2 + logf(sumP));
        }

    } else {
        // ============ PRODUCER: 4 warps (tid 256..383), GEMM to s_emis ======
        const int p = tid - 256;     // 0..127
        const int ty = p >> 4;       // 0..7  -> rows 4ty..4ty+3 (in tile)
        const int tx = p & 15;       // 0..15 -> cols 4tx..4tx+3
        const int arow = p >> 2;     // 0..31 (A staging row)
        const int ac4  = p & 3;      // A staging k-quad
        const float4 bias4 = *(const float4*)&bias[tx * 4];
        const float* hb = hidden + (size_t)b * TT * HH;

        for (int c = 0; c < 8; c++) {
            u64t acc[2][4];
#pragma unroll
            for (int pr = 0; pr < 2; pr++)
#pragma unroll
                for (int cc = 0; cc < 4; cc++) acc[pr][cc] = 0ull;

            const float* Atile = hb + (size_t)(32 * c) * HH;

            for (int kt = 0; kt < HH; kt += 16) {
                // stage A: 32x16, each thread 1 float4
                float4 av = *(const float4*)&Atile[(size_t)arow * HH + kt + ac4 * 4];
                s_As[(ac4 * 4 + 0) * 32 + arow] = av.x;
                s_As[(ac4 * 4 + 1) * 32 + arow] = av.y;
                s_As[(ac4 * 4 + 2) * 32 + arow] = av.z;
                s_As[(ac4 * 4 + 3) * 32 + arow] = av.w;
                // stage B dup-packed, layout [kk][cc][tx]
#pragma unroll
                for (int i = 0; i < 2; i++) {
                    int idx = p + 128 * i;
                    int brow = idx >> 4, bc4 = idx & 15;
                    float4 wv = *(const float4*)&Wm[(size_t)(kt + brow) * KK + bc4 * 4];
                    u64t* dst = &s_Bs2[brow * 64 + bc4];
                    dst[0]  = pack2(wv.x, wv.x);
                    dst[16] = pack2(wv.y, wv.y);
                    dst[32] = pack2(wv.z, wv.z);
                    dst[48] = pack2(wv.w, wv.w);
                }
                asm volatile("bar.sync 3, 128;" ::: "memory");

                const u64t* As2 = (const u64t*)s_As;
#pragma unroll
                for (int kk = 0; kk < 16; kk++) {
                    u64t a01 = As2[kk * 16 + 2 * ty];
                    u64t a23 = As2[kk * 16 + 2 * ty + 1];
                    const u64t* bp2 = &s_Bs2[kk * 64 + tx];
#pragma unroll
                    for (int cc = 0; cc < 4; cc++) {
                        u64t bd = bp2[cc * 16];
                        acc[0][cc] = ffma2(a01, bd, acc[0][cc]);
                        acc[1][cc] = ffma2(a23, bd, acc[1][cc]);
                    }
                }
                asm volatile("bar.sync 3, 128;" ::: "memory");
            }

            // emit rows 32c+4ty+{0..3}, cols 4tx..4tx+3 (+bias)
#pragma unroll
            for (int pr = 0; pr < 2; pr++) {
                float l0, h0, l1, h1, l2, h2, l3, h3;
                unpack2(acc[pr][0], &l0, &h0);
                unpack2(acc[pr][1], &l1, &h1);
                unpack2(acc[pr][2], &l2, &h2);
                unpack2(acc[pr][3], &l3, &h3);
                int r0 = 32 * c + 4 * ty + 2 * pr;
                *(float4*)&s_emis[(size_t)r0 * KK + tx * 4] =
                    make_float4(l0 + bias4.x, l1 + bias4.y, l2 + bias4.z, l3 + bias4.w);
                *(float4*)&s_emis[(size_t)(r0 + 1) * KK + tx * 4] =
                    make_float4(h0 + bias4.x, h1 + bias4.y, h2 + bias4.z, h3 + bias4.w);
            }
            asm volatile("bar.sync 3, 128;" ::: "memory");   // drain STS
            if (p == 0) st_release_sh(flag_a, c + 1);        // publish mini-tile
        }
    }
}

// ---------------------------------------------------------------------------
extern "C" void kernel_launch(void* const* d_in, const int* in_sizes, int n_in,
                              void* d_out, int out_size) {
    const float* hidden = (const float*)d_in[0];
    const int*   masks  = (const int*)d_in[1];
    const int*   target = (const int*)d_in[2];
    const float* Wm     = (const float*)d_in[3];
    const float* bias   = (const float*)d_in[4];
    const float* trans  = (const float*)d_in[5];
    float* out = (float*)d_out;

    cudaFuncSetAttribute(fused_kernel,
                         cudaFuncAttributeMaxDynamicSharedMemorySize, SMEM_BYTES);
    fused_kernel<<<BB, 384, SMEM_BYTES>>>(hidden, masks, target, Wm, bias, trans,
                                          out, out + (size_t)BB * TT);
}

// round 10
// speedup vs baseline: 1.8150x; 1.8150x over previous
#include <cuda_runtime.h>
#include <cuda_bf16.h>
#include <math.h>

#define BB 128
#define TT 256
#define HH 768
#define KK 64

typedef unsigned long long u64t;

__device__ float g_emis[BB * TT * KK];   // emissions scratch, 8 MB
__device__ int g_flags[BB * 4];          // per-64-row publish flags

// ---- packed f32x2 helpers ------------------------------------------------
__device__ __forceinline__ u64t ffma2(u64t a, u64t b, u64t c) {
    u64t d;
    asm("fma.rn.f32x2 %0, %1, %2, %3;" : "=l"(d) : "l"(a), "l"(b), "l"(c));
    return d;
}
__device__ __forceinline__ u64t pack2(float lo, float hi) {
    u64t d;
    unsigned a = __float_as_uint(lo), b = __float_as_uint(hi);
    asm("mov.b64 %0, {%1, %2};" : "=l"(d) : "r"(a), "r"(b));
    return d;
}
__device__ __forceinline__ void unpack2(u64t v, float* lo, float* hi) {
    unsigned a, b;
    asm("mov.b64 {%0, %1}, %2;" : "=r"(a), "=r"(b) : "l"(v));
    *lo = __uint_as_float(a);
    *hi = __uint_as_float(b);
}
__device__ __forceinline__ int ld_acq_gpu(const int* p) {
    int v;
    asm volatile("ld.acquire.gpu.global.b32 %0, [%1];" : "=r"(v) : "l"(p) : "memory");
    return v;
}
__device__ __forceinline__ void st_rel_gpu(int* p, int v) {
    asm volatile("st.release.gpu.global.b32 [%0], %1;" :: "l"(p), "r"(v) : "memory");
}

// ---------------------------------------------------------------------------
__global__ void zero_flags_kernel() {
    g_flags[blockIdx.x * 256 + threadIdx.x] = 0;
}

// ---------------------------------------------------------------------------
// Mixed kernel, grid=256 (one wave, 2 blocks/SM):
//   bid 0..127   : GEMM producer for batch bid — 4 sub-tiles of 64 rows,
//                  publishes g_flags[b*4+s] after each (release).
//   bid 128..255 : CRF consumer for batch bid-128 — round-8 body, emission
//                  prefetch gated on acquire-loads of the flags.
// ---------------------------------------------------------------------------
__global__ __launch_bounds__(256, 2) void mixed_kernel(
    const float* __restrict__ hidden,
    const int* __restrict__ masks,
    const int* __restrict__ target,
    const float* __restrict__ Wm,
    const float* __restrict__ bias,
    const float* __restrict__ trans_g,
    float* __restrict__ out_dec,
    float* __restrict__ out_ll)
{
    const int tid = threadIdx.x;

    if (blockIdx.x < BB) {
        // ==================== GEMM PRODUCER (batch b) =======================
        __shared__ float s_As[16 * 68];        // A tile transposed [kk][row]
        __shared__ u64t  s_Bs2[16 * 64];       // B dup-packed [kk][cc*16+tx]

        const int b = blockIdx.x;
        const int ty = tid >> 4, tx = tid & 15;       // thread tile 4x4
        const int arow = tid >> 2, ac4 = tid & 3;     // A staging
        const int brow = tid >> 4, bc4 = tid & 15;    // B staging
        const float4 bias4 = *(const float4*)&bias[tx * 4];
        const float* hb = hidden + (size_t)b * TT * HH;
        float* eb = &g_emis[(size_t)b * TT * KK];

        for (int s = 0; s < 4; s++) {
            const float* Atile = hb + (size_t)(64 * s) * HH;

            u64t acc[2][4];
#pragma unroll
            for (int pr = 0; pr < 2; pr++)
#pragma unroll
                for (int cc = 0; cc < 4; cc++) acc[pr][cc] = 0ull;

            // prefetch k-tile 0
            float4 aReg = *(const float4*)&Atile[(size_t)arow * HH + ac4 * 4];
            float4 bReg = *(const float4*)&Wm[(size_t)brow * KK + bc4 * 4];

            for (int kt = 0; kt < HH; kt += 16) {
                s_As[(ac4 * 4 + 0) * 68 + arow] = aReg.x;
                s_As[(ac4 * 4 + 1) * 68 + arow] = aReg.y;
                s_As[(ac4 * 4 + 2) * 68 + arow] = aReg.z;
                s_As[(ac4 * 4 + 3) * 68 + arow] = aReg.w;
                {
                    u64t* dst = &s_Bs2[brow * 64 + bc4];
                    dst[0]  = pack2(bReg.x, bReg.x);
                    dst[16] = pack2(bReg.y, bReg.y);
                    dst[32] = pack2(bReg.z, bReg.z);
                    dst[48] = pack2(bReg.w, bReg.w);
                }
                __syncthreads();

                if (kt + 16 < HH) {
                    aReg = *(const float4*)&Atile[(size_t)arow * HH + kt + 16 + ac4 * 4];
                    bReg = *(const float4*)&Wm[(size_t)(kt + 16 + brow) * KK + bc4 * 4];
                }

                const u64t* As2 = (const u64t*)s_As;
#pragma unroll
                for (int kk = 0; kk < 16; kk++) {
                    u64t a01 = As2[kk * 34 + 2 * ty];
                    u64t a23 = As2[kk * 34 + 2 * ty + 1];
                    const u64t* bp2 = &s_Bs2[kk * 64 + tx];
#pragma unroll
                    for (int cc = 0; cc < 4; cc++) {
                        u64t bd = bp2[cc * 16];
                        acc[0][cc] = ffma2(a01, bd, acc[0][cc]);
                        acc[1][cc] = ffma2(a23, bd, acc[1][cc]);
                    }
                }
                __syncthreads();
            }

            // emit 64x64 sub-tile (+bias)
#pragma unroll
            for (int pr = 0; pr < 2; pr++) {
                float l0, h0, l1, h1, l2, h2, l3, h3;
                unpack2(acc[pr][0], &l0, &h0);
                unpack2(acc[pr][1], &l1, &h1);
                unpack2(acc[pr][2], &l2, &h2);
                unpack2(acc[pr][3], &l3, &h3);
                int r0 = 64 * s + 4 * ty + 2 * pr;
                *(float4*)&eb[(size_t)r0 * KK + tx * 4] =
                    make_float4(l0 + bias4.x, l1 + bias4.y, l2 + bias4.z, l3 + bias4.w);
                *(float4*)&eb[(size_t)(r0 + 1) * KK + tx * 4] =
                    make_float4(h0 + bias4.x, h1 + bias4.y, h2 + bias4.z, h3 + bias4.w);
            }
            __threadfence();
            __syncthreads();
            if (tid == 0) st_rel_gpu(&g_flags[b * 4 + s], 1);
        }
        return;
    }

    // ======================== CRF CONSUMER (batch b) ========================
    __shared__ __align__(16) float s_v[3][64];
    __shared__ __align__(16) float s_P[2][64];
    __shared__ __align__(16) float s_tt[64 * 68];
    __shared__ float s_red[8];
    __shared__ int s_len_v, s_len_f;
    __shared__ int s_path[TT];
    __shared__ unsigned char s_bp[(TT - 1) * KK];

    const int b = blockIdx.x - BB;
    const float* emisb = &g_emis[(size_t)b * TT * KK];
    const int* flags = &g_flags[b * 4];

    if (tid < 128) {
        // ================= VITERBI: 4 warps, 2 threads per state ============
        if (tid < 32) {
            int acc = 0;
#pragma unroll
            for (int i = 0; i < 8; i++) acc += masks[b * TT + tid + 32 * i];
#pragma unroll
            for (int o = 16; o; o >>= 1) acc += __shfl_xor_sync(0xFFFFFFFFu, acc, o);
            if (tid == 0) s_len_v = acc;
        }

        const int j = tid >> 1;
        const int h = tid & 1;
        const int k0 = h * 32;

        for (int i = tid; i < 4096; i += 128) {
            int k = i >> 6, jj = i & 63;
            s_tt[jj * 68 + k] = trans_g[i];
        }
        float Tcol[32];
#pragma unroll
        for (int kk = 0; kk < 32; kk++)
            Tcol[kk] = trans_g[(k0 + kk) * KK + j];

        int have = 0;
        while (have < 1) {
            if (ld_acq_gpu(&flags[0])) have = 1; else __nanosleep(64);
        }

        float e0 = emisb[j];
        float ecur[4];
#pragma unroll
        for (int i = 0; i < 4; i++) ecur[i] = emisb[(size_t)(1 + i) * KK + j];

        float prevV = e0;
        if (h == 0) s_v[0][j] = e0;
        asm volatile("bar.sync 1, 128;" ::: "memory");
        const int len = s_len_v;
        int rbuf = 0;

        float pqm[8];
        float pbv = 0.f;
        int pvalid = 0;
        int pt = 0;

        for (int tb = 1; tb < TT; tb += 4) {
            int needrow = tb + 7; if (needrow > 255) needrow = 255;
            int needf = (needrow >> 6) + 1;
            while (have < needf) {
                if (ld_acq_gpu(&flags[have])) have++; else __nanosleep(64);
            }

            float enext[4];
#pragma unroll
            for (int i = 0; i < 4; i++) {
                int tt = tb + 4 + i;
                enext[i] = (tt < TT) ? emisb[(size_t)tt * KK + j] : 0.f;
            }
#pragma unroll
            for (int i = 0; i < 4; i++) {
                const int t = tb + i;
                if (t >= TT) break;

                const int wbuf = (rbuf == 2) ? 0 : rbuf + 1;
                const int obuf = (wbuf == 2) ? 0 : wbuf + 1;

                const float4* V4 = (const float4*)&s_v[rbuf][k0];
                float4 v0 = V4[0], v1 = V4[1], v2 = V4[2], v3 = V4[3];
                float4 v4 = V4[4], v5 = V4[5], v6 = V4[6], v7 = V4[7];

                if (pvalid) {
                    int li = 255;
                    if (pvalid == 1) {
                        int qq = 8;
#pragma unroll
                        for (int m = 7; m >= 0; m--)
                            qq = (pqm[m] == pbv) ? m : qq;
                        if (qq < 8) {
                            int kq = k0 + qq * 4;
                            float4 vq = *(const float4*)&s_v[obuf][kq];
                            float4 tq = *(const float4*)&s_tt[j * 68 + kq];
                            float c0 = vq.x + tq.x, c1 = vq.y + tq.y;
                            float c2 = vq.z + tq.z, c3 = vq.w + tq.w;
                            li = kq + 3;
                            li = (c2 == pbv) ? kq + 2 : li;
                            li = (c1 == pbv) ? kq + 1 : li;
                            li = (c0 == pbv) ? kq : li;
                        }
                        int oi = __shfl_xor_sync(0xFFFFFFFFu, li, 1);
                        li = min(li, oi);
                    } else {
                        li = j;
                    }
                    if (h == 0) s_bp[(pt - 1) * KK + j] = (unsigned char)li;
                }

                float qm[8];
                {
                    float c0, c1, c2, c3;
                    c0 = v0.x + Tcol[0];  c1 = v0.y + Tcol[1];
                    c2 = v0.z + Tcol[2];  c3 = v0.w + Tcol[3];
                    qm[0] = fmaxf(fmaxf(c0, c1), fmaxf(c2, c3));
                    c0 = v1.x + Tcol[4];  c1 = v1.y + Tcol[5];
                    c2 = v1.z + Tcol[6];  c3 = v1.w + Tcol[7];
                    qm[1] = fmaxf(fmaxf(c0, c1), fmaxf(c2, c3));
                    c0 = v2.x + Tcol[8];  c1 = v2.y + Tcol[9];
                    c2 = v2.z + Tcol[10]; c3 = v2.w + Tcol[11];
                    qm[2] = fmaxf(fmaxf(c0, c1), fmaxf(c2, c3));
                    c0 = v3.x + Tcol[12]; c1 = v3.y + Tcol[13];
                    c2 = v3.z + Tcol[14]; c3 = v3.w + Tcol[15];
                    qm[3] = fmaxf(fmaxf(c0, c1), fmaxf(c2, c3));
                    c0 = v4.x + Tcol[16]; c1 = v4.y + Tcol[17];
                    c2 = v4.z + Tcol[18]; c3 = v4.w + Tcol[19];
                    qm[4] = fmaxf(fmaxf(c0, c1), fmaxf(c2, c3));
                    c0 = v5.x + Tcol[20]; c1 = v5.y + Tcol[21];
                    c2 = v5.z + Tcol[22]; c3 = v5.w + Tcol[23];
                    qm[5] = fmaxf(fmaxf(c0, c1), fmaxf(c2, c3));
                    c0 = v6.x + Tcol[24]; c1 = v6.y + Tcol[25];
                    c2 = v6.z + Tcol[26]; c3 = v6.w + Tcol[27];
                    qm[6] = fmaxf(fmaxf(c0, c1), fmaxf(c2, c3));
                    c0 = v7.x + Tcol[28]; c1 = v7.y + Tcol[29];
                    c2 = v7.z + Tcol[30]; c3 = v7.w + Tcol[31];
                    qm[7] = fmaxf(fmaxf(c0, c1), fmaxf(c2, c3));
                }
                float m0 = fmaxf(qm[0], qm[1]), m1 = fmaxf(qm[2], qm[3]);
                float m2 = fmaxf(qm[4], qm[5]), m3 = fmaxf(qm[6], qm[7]);
                float bv = fmaxf(fmaxf(m0, m1), fmaxf(m2, m3));
                bv = fmaxf(bv, __shfl_xor_sync(0xFFFFFFFFu, bv, 1));

                float newv = (t < len) ? (bv + ecur[i]) : prevV;
                if (h == 0) s_v[wbuf][j] = newv;
                prevV = newv;

#pragma unroll
                for (int m = 0; m < 8; m++) pqm[m] = qm[m];
                pbv = bv;
                pvalid = (t < len) ? 1 : 2;
                pt = t;

                asm volatile("bar.sync 1, 128;" ::: "memory");
                rbuf = wbuf;
            }
#pragma unroll
            for (int i = 0; i < 4; i++) ecur[i] = enext[i];
        }

        {   // final pending bp (t = 255)
            const int obuf = (rbuf == 0) ? 2 : rbuf - 1;
            int li = 255;
            if (pvalid == 1) {
                int qq = 8;
#pragma unroll
                for (int m = 7; m >= 0; m--)
                    qq = (pqm[m] == pbv) ? m : qq;
                if (qq < 8) {
                    int kq = k0 + qq * 4;
                    float4 vq = *(const float4*)&s_v[obuf][kq];
                    float4 tq = *(const float4*)&s_tt[j * 68 + kq];
                    float c0 = vq.x + tq.x, c1 = vq.y + tq.y;
                    float c2 = vq.z + tq.z, c3 = vq.w + tq.w;
                    li = kq + 3;
                    li = (c2 == pbv) ? kq + 2 : li;
                    li = (c1 == pbv) ? kq + 1 : li;
                    li = (c0 == pbv) ? kq : li;
                }
                int oi = __shfl_xor_sync(0xFFFFFFFFu, li, 1);
                li = min(li, oi);
            } else {
                li = j;
            }
            if (h == 0) s_bp[(pt - 1) * KK + j] = (unsigned char)li;
        }
        asm volatile("bar.sync 1, 128;" ::: "memory");

        if (tid == 0) {
            float bvv = s_v[rbuf][0];
            int tg = 0;
#pragma unroll
            for (int k = 1; k < KK; k++)
                if (s_v[rbuf][k] > bvv) { bvv = s_v[rbuf][k]; tg = k; }
            s_path[TT - 1] = tg;
            for (int t = TT - 1; t >= 1; t--) {
                tg = s_bp[(t - 1) * KK + tg];
                s_path[t - 1] = tg;
            }
        }
        asm volatile("bar.sync 1, 128;" ::: "memory");
#pragma unroll
        for (int i = 0; i < 2; i++) {
            int tt = tid + 128 * i;
            out_dec[(size_t)b * TT + tt] = (float)((tt < len) ? s_path[tt] : 0);
        }

    } else {
        // ============ FORWARD: 4 warps (tid 128..255), 2 threads/state ======
        const int ft = tid - 128;

        if (ft < 32) {
            int acc = 0;
#pragma unroll
            for (int i = 0; i < 8; i++) acc += masks[b * TT + ft + 32 * i];
#pragma unroll
            for (int o = 16; o; o >>= 1) acc += __shfl_xor_sync(0xFFFFFFFFu, acc, o);
            if (ft == 0) s_len_f = acc;
        }

        const int j = ft >> 1;
        const int h = ft & 1;
        const int k0 = h * 32;

        u64t E2[16];
#pragma unroll
        for (int m = 0; m < 16; m++) {
            float t0 = trans_g[(k0 + 2 * m) * KK + j];
            float t1 = trans_g[(k0 + 2 * m + 1) * KK + j];
            E2[m] = pack2(expf(t0), expf(t1));
        }

        int have = 0;
        while (have < 1) {
            if (ld_acq_gpu(&flags[0])) have = 1; else __nanosleep(64);
        }

        float e0 = emisb[j];
        float ecur[4];
#pragma unroll
        for (int i = 0; i < 4; i++) ecur[i] = emisb[(size_t)(1 + i) * KK + j];

        float prevP = __expf(e0);
        int iexp = 0;
        if (h == 0) s_P[0][j] = prevP;
        asm volatile("bar.sync 2, 128;" ::: "memory");
        const int len = s_len_f;
        int buf = 0;

        for (int tb = 1; tb < TT; tb += 4) {
            int needrow = tb + 7; if (needrow > 255) needrow = 255;
            int needf = (needrow >> 6) + 1;
            while (have < needf) {
                if (ld_acq_gpu(&flags[have])) have++; else __nanosleep(64);
            }

            float enext[4];
#pragma unroll
            for (int i = 0; i < 4; i++) {
                int tt = tb + 4 + i;
                enext[i] = (tt < TT) ? emisb[(size_t)tt * KK + j] : 0.f;
            }
            float eexp[4];
#pragma unroll
            for (int i = 0; i < 4; i++) eexp[i] = __expf(ecur[i]);

#pragma unroll
            for (int i = 0; i < 4; i++) {
                const int t = tb + i;
                if (t >= TT) break;

                float p0 = s_P[buf][0];
                const u64t* P2 = (const u64t*)&s_P[buf][k0];
                u64t s0 = 0ull, s1 = 0ull, s2 = 0ull, s3 = 0ull;
#pragma unroll
                for (int m = 0; m < 4; m++) {
                    s0 = ffma2(P2[4 * m + 0], E2[4 * m + 0], s0);
                    s1 = ffma2(P2[4 * m + 1], E2[4 * m + 1], s1);
                    s2 = ffma2(P2[4 * m + 2], E2[4 * m + 2], s2);
                    s3 = ffma2(P2[4 * m + 3], E2[4 * m + 3], s3);
                }
                float l0, h0, l1, h1, l2, h2, l3, h3;
                unpack2(s0, &l0, &h0);
                unpack2(s1, &l1, &h1);
                unpack2(s2, &l2, &h2);
                unpack2(s3, &l3, &h3);
                float S = ((l0 + h0) + (l1 + h1)) + ((l2 + h2) + (l3 + h3));
                S += __shfl_xor_sync(0xFFFFFFFFu, S, 1);

                int e0i = (int)(__float_as_uint(p0) >> 23);
                float scale = __uint_as_float((unsigned)(254 - e0i) << 23);
                if (t < len) {
                    prevP = S * scale * eexp[i];
                    iexp += e0i - 127;
                }
                if (h == 0) s_P[buf ^ 1][j] = prevP;
                asm volatile("bar.sync 2, 128;" ::: "memory");
                buf ^= 1;
            }
#pragma unroll
            for (int i = 0; i < 4; i++) ecur[i] = enext[i];
        }

        float sp = (h == 0) ? prevP : 0.f;
#pragma unroll
        for (int o = 16; o; o >>= 1) sp += __shfl_xor_sync(0xFFFFFFFFu, sp, o);
        if ((ft & 31) == 0) s_red[ft >> 5] = sp;

        float uacc = 0.f;
#pragma unroll
        for (int i = 0; i < 2; i++) {
            int tt = ft + 128 * i;
            if (tt < len) {
                int tg = target[b * TT + tt];
                uacc += emisb[(size_t)tt * KK + tg];
                if (tt >= 1) uacc += trans_g[target[b * TT + tt - 1] * KK + tg];
            }
        }
#pragma unroll
        for (int o = 16; o; o >>= 1) uacc += __shfl_xor_sync(0xFFFFFFFFu, uacc, o);
        if ((ft & 31) == 0) s_red[4 + (ft >> 5)] = uacc;
        asm volatile("bar.sync 2, 128;" ::: "memory");

        if (ft == 0) {
            float sumP = s_red[0] + s_red[1] + s_red[2] + s_red[3];
            float score = s_red[4] + s_red[5] + s_red[6] + s_red[7];
            const float LN2 = 0.69314718055994531f;
            out_ll[b] = score - ((float)iexp * LN2 + logf(sumP));
        }
    }
}

// ---------------------------------------------------------------------------
extern "C" void kernel_launch(void* const* d_in, const int* in_sizes, int n_in,
                              void* d_out, int out_size) {
    const float* hidden = (const float*)d_in[0];
    const int*   masks  = (const int*)d_in[1];
    const int*   target = (const int*)d_in[2];
    const float* Wm     = (const float*)d_in[3];
    const float* bias   = (const float*)d_in[4];
    const float* trans  = (const float*)d_in[5];
    float* out = (float*)d_out;

    zero_flags_kernel<<<2, 256>>>();
    mixed_kernel<<<2 * BB, 256>>>(hidden, masks, target, Wm, bias, trans,
                                  out, out + (size_t)BB * TT);
}

// round 11
// speedup vs baseline: 2.4297x; 1.3387x over previous
#include <cuda_runtime.h>
#include <cuda_bf16.h>
#include <math.h>

#define BB 128
#define TT 256
#define HH 768
#define KK 64

typedef unsigned long long u64t;

__device__ float g_emis[BB * TT * KK];   // emissions scratch, 8 MB
__device__ int g_flags[2 * BB];          // one flag per 128-row half-batch

// ---- packed f32x2 helpers ------------------------------------------------
__device__ __forceinline__ u64t ffma2(u64t a, u64t b, u64t c) {
    u64t d;
    asm("fma.rn.f32x2 %0, %1, %2, %3;" : "=l"(d) : "l"(a), "l"(b), "l"(c));
    return d;
}
__device__ __forceinline__ u64t pack2(float lo, float hi) {
    u64t d;
    unsigned a = __float_as_uint(lo), b = __float_as_uint(hi);
    asm("mov.b64 %0, {%1, %2};" : "=l"(d) : "r"(a), "r"(b));
    return d;
}
__device__ __forceinline__ void unpack2(u64t v, float* lo, float* hi) {
    unsigned a, b;
    asm("mov.b64 {%0, %1}, %2;" : "=r"(a), "=r"(b) : "l"(v));
    *lo = __uint_as_float(a);
    *hi = __uint_as_float(b);
}
__device__ __forceinline__ int ld_acq_gpu(const int* p) {
    int v;
    asm volatile("ld.acquire.gpu.global.b32 %0, [%1];" : "=r"(v) : "l"(p) : "memory");
    return v;
}
__device__ __forceinline__ void st_rel_gpu(int* p, int v) {
    asm volatile("st.release.gpu.global.b32 [%0], %1;" :: "l"(p), "r"(v) : "memory");
}

__global__ void zero_flags_kernel() {
    g_flags[threadIdx.x] = 0;
}

// Phase-B smem offsets (bytes); phase A uses [0, 12544) for As/Bs.
#define OFF_V     0        // 3*64*4   = 768
#define OFF_P     768      // 2*64*4   = 512
#define OFF_RED   1280     // 8*4      = 32
#define OFF_MISC  1312     // 4*4      = 16
#define OFF_PATH  1328     // 256*4    = 1024
#define OFF_TT    2368     // 64*68*4  = 17408
#define OFF_BP    19776    // 255*64   = 16320  -> 36096
#define OFF_AS    0        // phase A: 16*132*4 = 8448
#define OFF_BS    8448     // phase A: 16*64*4  = 4096 -> 12544
#define SMEM_BYTES 36864

// ---------------------------------------------------------------------------
// Single kernel, grid=256, all blocks resident (2/SM):
//  Phase A (all): GEMM emis rows [bid*128, bid*128+128)  (round-8 verbatim)
//  Phase B (bid<128): CRF for batch bid (round-8 verbatim); others exit.
//  Placement (b, b+148) => CRF blocks end up alone on their SM in phase B.
// ---------------------------------------------------------------------------
__global__ __launch_bounds__(256, 2) void fused2_kernel(
    const float* __restrict__ hidden,
    const int* __restrict__ masks,
    const int* __restrict__ target,
    const float* __restrict__ Wm,
    const float* __restrict__ bias,
    const float* __restrict__ trans_g,
    float* __restrict__ out_dec,
    float* __restrict__ out_ll)
{
    extern __shared__ __align__(16) char smem[];
    const int tid = threadIdx.x;
    const int bid = blockIdx.x;

    // ========================= PHASE A: GEMM ================================
    {
        float* s_As = (float*)(smem + OFF_AS);   // [16][132] transposed A tile
        float* s_Bs = (float*)(smem + OFF_BS);   // [16][64]

        const int m0 = bid * 128;
        const int ty = tid >> 4;
        const int tx = tid & 15;

        u64t acc2[4][4];
#pragma unroll
        for (int rp = 0; rp < 4; rp++)
#pragma unroll
            for (int c = 0; c < 4; c++) acc2[rp][c] = 0ull;

        const int arow0 = (tid) >> 2,       ac40 = (tid) & 3;
        const int arow1 = (tid + 256) >> 2, ac41 = (tid + 256) & 3;
        const int brow = tid >> 4, bc4 = tid & 15;

        float4 aReg0 = *(const float4*)&hidden[(size_t)(m0 + arow0) * HH + ac40 * 4];
        float4 aReg1 = *(const float4*)&hidden[(size_t)(m0 + arow1) * HH + ac41 * 4];
        float4 bReg  = *(const float4*)&Wm[(size_t)(brow) * KK + bc4 * 4];

        for (int kt = 0; kt < HH; kt += 16) {
            s_As[(ac40 * 4 + 0) * 132 + arow0] = aReg0.x;
            s_As[(ac40 * 4 + 1) * 132 + arow0] = aReg0.y;
            s_As[(ac40 * 4 + 2) * 132 + arow0] = aReg0.z;
            s_As[(ac40 * 4 + 3) * 132 + arow0] = aReg0.w;
            s_As[(ac41 * 4 + 0) * 132 + arow1] = aReg1.x;
            s_As[(ac41 * 4 + 1) * 132 + arow1] = aReg1.y;
            s_As[(ac41 * 4 + 2) * 132 + arow1] = aReg1.z;
            s_As[(ac41 * 4 + 3) * 132 + arow1] = aReg1.w;
            *(float4*)&s_Bs[brow * 64 + bc4 * 4] = bReg;
            __syncthreads();

            if (kt + 16 < HH) {
                aReg0 = *(const float4*)&hidden[(size_t)(m0 + arow0) * HH + kt + 16 + ac40 * 4];
                aReg1 = *(const float4*)&hidden[(size_t)(m0 + arow1) * HH + kt + 16 + ac41 * 4];
                bReg  = *(const float4*)&Wm[(size_t)(kt + 16 + brow) * KK + bc4 * 4];
            }

#pragma unroll
            for (int kk = 0; kk < 16; kk++) {
                const u64t* ap = (const u64t*)&s_As[kk * 132 + ty * 8];
                u64t a2[4];
#pragma unroll
                for (int rp = 0; rp < 4; rp++) a2[rp] = ap[rp];
                float4 bv = *(const float4*)&s_Bs[kk * 64 + tx * 4];
                u64t bd[4];
                bd[0] = pack2(bv.x, bv.x);
                bd[1] = pack2(bv.y, bv.y);
                bd[2] = pack2(bv.z, bv.z);
                bd[3] = pack2(bv.w, bv.w);
#pragma unroll
                for (int rp = 0; rp < 4; rp++)
#pragma unroll
                    for (int c = 0; c < 4; c++)
                        acc2[rp][c] = ffma2(a2[rp], bd[c], acc2[rp][c]);
            }
            __syncthreads();
        }

        float4 bb = *(const float4*)&bias[tx * 4];
        const float bbv[4] = {bb.x, bb.y, bb.z, bb.w};
#pragma unroll
        for (int rp = 0; rp < 4; rp++) {
            float o0[4], o1[4];
#pragma unroll
            for (int c = 0; c < 4; c++) {
                float lo, hi;
                unpack2(acc2[rp][c], &lo, &hi);
                o0[c] = lo + bbv[c];
                o1[c] = hi + bbv[c];
            }
            int row = m0 + ty * 8 + 2 * rp;
            *(float4*)&g_emis[(size_t)row * KK + tx * 4]       = make_float4(o0[0], o0[1], o0[2], o0[3]);
            *(float4*)&g_emis[(size_t)(row + 1) * KK + tx * 4] = make_float4(o1[0], o1[1], o1[2], o1[3]);
        }
        __threadfence();
        __syncthreads();                       // phase-A smem reads complete
        if (tid == 0) st_rel_gpu(&g_flags[bid], 1);
    }

    if (bid >= BB) return;

    // ========================= PHASE B: CRF (batch bid) =====================
    float (*s_v)[64] = (float(*)[64])(smem + OFF_V);
    float (*s_P)[64] = (float(*)[64])(smem + OFF_P);
    float* s_red = (float*)(smem + OFF_RED);
    int*   s_misc = (int*)(smem + OFF_MISC);   // [0]=len_v [1]=len_f
    int*   s_path = (int*)(smem + OFF_PATH);
    float* s_tt = (float*)(smem + OFF_TT);
    unsigned char* s_bp = (unsigned char*)(smem + OFF_BP);

    const int b = bid;
    const float* emisb = &g_emis[(size_t)b * TT * KK];
    const int* f0p = &g_flags[2 * b];
    const int* f1p = &g_flags[2 * b + 1];

    if (tid < 128) {
        // ================= VITERBI: 4 warps, 2 threads per state ============
        if (tid < 32) {
            int acc = 0;
#pragma unroll
            for (int i = 0; i < 8; i++) acc += masks[b * TT + tid + 32 * i];
#pragma unroll
            for (int o = 16; o; o >>= 1) acc += __shfl_xor_sync(0xFFFFFFFFu, acc, o);
            if (tid == 0) s_misc[0] = acc;
        }

        const int j = tid >> 1;
        const int h = tid & 1;
        const int k0 = h * 32;

        for (int i = tid; i < 4096; i += 128) {
            int k = i >> 6, jj = i & 63;
            s_tt[jj * 68 + k] = trans_g[i];
        }
        float Tcol[32];
#pragma unroll
        for (int kk = 0; kk < 32; kk++)
            Tcol[kk] = trans_g[(k0 + kk) * KK + j];

        while (ld_acq_gpu(f0p) == 0) __nanosleep(64);

        float e0 = emisb[j];
        float ecur[4];
#pragma unroll
        for (int i = 0; i < 4; i++) ecur[i] = emisb[(size_t)(1 + i) * KK + j];

        float prevV = e0;
        if (h == 0) s_v[0][j] = e0;
        asm volatile("bar.sync 1, 128;" ::: "memory");
        const int len = s_misc[0];
        int rbuf = 0;
        int have1 = 0;

        float pqm[8];
        float pbv = 0.f;
        int pvalid = 0;
        int pt = 0;

        for (int tb = 1; tb < TT; tb += 4) {
            int needrow = tb + 7; if (needrow > 255) needrow = 255;
            if (needrow >= 128 && !have1) {
                while (ld_acq_gpu(f1p) == 0) __nanosleep(64);
                have1 = 1;
            }

            float enext[4];
#pragma unroll
            for (int i = 0; i < 4; i++) {
                int tt = tb + 4 + i;
                enext[i] = (tt < TT) ? emisb[(size_t)tt * KK + j] : 0.f;
            }
#pragma unroll
            for (int i = 0; i < 4; i++) {
                const int t = tb + i;
                if (t >= TT) break;

                const int wbuf = (rbuf == 2) ? 0 : rbuf + 1;
                const int obuf = (wbuf == 2) ? 0 : wbuf + 1;

                const float4* V4 = (const float4*)&s_v[rbuf][k0];
                float4 v0 = V4[0], v1 = V4[1], v2 = V4[2], v3 = V4[3];
                float4 v4 = V4[4], v5 = V4[5], v6 = V4[6], v7 = V4[7];

                if (pvalid) {
                    int li = 255;
                    if (pvalid == 1) {
                        int qq = 8;
#pragma unroll
                        for (int m = 7; m >= 0; m--)
                            qq = (pqm[m] == pbv) ? m : qq;
                        if (qq < 8) {
                            int kq = k0 + qq * 4;
                            float4 vq = *(const float4*)&s_v[obuf][kq];
                            float4 tq = *(const float4*)&s_tt[j * 68 + kq];
                            float c0 = vq.x + tq.x, c1 = vq.y + tq.y;
                            float c2 = vq.z + tq.z, c3 = vq.w + tq.w;
                            li = kq + 3;
                            li = (c2 == pbv) ? kq + 2 : li;
                            li = (c1 == pbv) ? kq + 1 : li;
                            li = (c0 == pbv) ? kq : li;
                        }
                        int oi = __shfl_xor_sync(0xFFFFFFFFu, li, 1);
                        li = min(li, oi);
                    } else {
                        li = j;
                    }
                    if (h == 0) s_bp[(pt - 1) * KK + j] = (unsigned char)li;
                }

                float qm[8];
                {
                    float c0, c1, c2, c3;
                    c0 = v0.x + Tcol[0];  c1 = v0.y + Tcol[1];
                    c2 = v0.z + Tcol[2];  c3 = v0.w + Tcol[3];
                    qm[0] = fmaxf(fmaxf(c0, c1), fmaxf(c2, c3));
                    c0 = v1.x + Tcol[4];  c1 = v1.y + Tcol[5];
                    c2 = v1.z + Tcol[6];  c3 = v1.w + Tcol[7];
                    qm[1] = fmaxf(fmaxf(c0, c1), fmaxf(c2, c3));
                    c0 = v2.x + Tcol[8];  c1 = v2.y + Tcol[9];
                    c2 = v2.z + Tcol[10]; c3 = v2.w + Tcol[11];
                    qm[2] = fmaxf(fmaxf(c0, c1), fmaxf(c2, c3));
                    c0 = v3.x + Tcol[12]; c1 = v3.y + Tcol[13];
                    c2 = v3.z + Tcol[14]; c3 = v3.w + Tcol[15];
                    qm[3] = fmaxf(fmaxf(c0, c1), fmaxf(c2, c3));
                    c0 = v4.x + Tcol[16]; c1 = v4.y + Tcol[17];
                    c2 = v4.z + Tcol[18]; c3 = v4.w + Tcol[19];
                    qm[4] = fmaxf(fmaxf(c0, c1), fmaxf(c2, c3));
                    c0 = v5.x + Tcol[20]; c1 = v5.y + Tcol[21];
                    c2 = v5.z + Tcol[22]; c3 = v5.w + Tcol[23];
                    qm[5] = fmaxf(fmaxf(c0, c1), fmaxf(c2, c3));
                    c0 = v6.x + Tcol[24]; c1 = v6.y + Tcol[25];
                    c2 = v6.z + Tcol[26]; c3 = v6.w + Tcol[27];
                    qm[6] = fmaxf(fmaxf(c0, c1), fmaxf(c2, c3));
                    c0 = v7.x + Tcol[28]; c1 = v7.y + Tcol[29];
                    c2 = v7.z + Tcol[30]; c3 = v7.w + Tcol[31];
                    qm[7] = fmaxf(fmaxf(c0, c1), fmaxf(c2, c3));
                }
                float m0 = fmaxf(qm[0], qm[1]), m1 = fmaxf(qm[2], qm[3]);
                float m2 = fmaxf(qm[4], qm[5]), m3 = fmaxf(qm[6], qm[7]);
                float bv = fmaxf(fmaxf(m0, m1), fmaxf(m2, m3));
                bv = fmaxf(bv, __shfl_xor_sync(0xFFFFFFFFu, bv, 1));

                float newv = (t < len) ? (bv + ecur[i]) : prevV;
                if (h == 0) s_v[wbuf][j] = newv;
                prevV = newv;

#pragma unroll
                for (int m = 0; m < 8; m++) pqm[m] = qm[m];
                pbv = bv;
                pvalid = (t < len) ? 1 : 2;
                pt = t;

                asm volatile("bar.sync 1, 128;" ::: "memory");
                rbuf = wbuf;
            }
#pragma unroll
            for (int i = 0; i < 4; i++) ecur[i] = enext[i];
        }

        {   // final pending bp (t = 255)
            const int obuf = (rbuf == 0) ? 2 : rbuf - 1;
            int li = 255;
            if (pvalid == 1) {
                int qq = 8;
#pragma unroll
                for (int m = 7; m >= 0; m--)
                    qq = (pqm[m] == pbv) ? m : qq;
                if (qq < 8) {
                    int kq = k0 + qq * 4;
                    float4 vq = *(const float4*)&s_v[obuf][kq];
                    float4 tq = *(const float4*)&s_tt[j * 68 + kq];
                    float c0 = vq.x + tq.x, c1 = vq.y + tq.y;
                    float c2 = vq.z + tq.z, c3 = vq.w + tq.w;
                    li = kq + 3;
                    li = (c2 == pbv) ? kq + 2 : li;
                    li = (c1 == pbv) ? kq + 1 : li;
                    li = (c0 == pbv) ? kq : li;
                }
                int oi = __shfl_xor_sync(0xFFFFFFFFu, li, 1);
                li = min(li, oi);
            } else {
                li = j;
            }
            if (h == 0) s_bp[(pt - 1) * KK + j] = (unsigned char)li;
        }
        asm volatile("bar.sync 1, 128;" ::: "memory");

        if (tid == 0) {
            float bvv = s_v[rbuf][0];
            int tg = 0;
#pragma unroll
            for (int k = 1; k < KK; k++)
                if (s_v[rbuf][k] > bvv) { bvv = s_v[rbuf][k]; tg = k; }
            s_path[TT - 1] = tg;
            for (int t = TT - 1; t >= 1; t--) {
                tg = s_bp[(t - 1) * KK + tg];
                s_path[t - 1] = tg;
            }
        }
        asm volatile("bar.sync 1, 128;" ::: "memory");
#pragma unroll
        for (int i = 0; i < 2; i++) {
            int tt = tid + 128 * i;
            out_dec[(size_t)b * TT + tt] = (float)((tt < len) ? s_path[tt] : 0);
        }

    } else {
        // ============ FORWARD: 4 warps (tid 128..255), 2 threads/state ======
        const int ft = tid - 128;

        if (ft < 32) {
            int acc = 0;
#pragma unroll
            for (int i = 0; i < 8; i++) acc += masks[b * TT + ft + 32 * i];
#pragma unroll
            for (int o = 16; o; o >>= 1) acc += __shfl_xor_sync(0xFFFFFFFFu, acc, o);
            if (ft == 0) s_misc[1] = acc;
        }

        const int j = ft >> 1;
        const int h = ft & 1;
        const int k0 = h * 32;

        u64t E2[16];
#pragma unroll
        for (int m = 0; m < 16; m++) {
            float t0 = trans_g[(k0 + 2 * m) * KK + j];
            float t1 = trans_g[(k0 + 2 * m + 1) * KK + j];
            E2[m] = pack2(expf(t0), expf(t1));
        }

        while (ld_acq_gpu(f0p) == 0) __nanosleep(64);

        float e0 = emisb[j];
        float ecur[4];
#pragma unroll
        for (int i = 0; i < 4; i++) ecur[i] = emisb[(size_t)(1 + i) * KK + j];

        float prevP = __expf(e0);
        int iexp = 0;
        if (h == 0) s_P[0][j] = prevP;
        asm volatile("bar.sync 2, 128;" ::: "memory");
        const int len = s_misc[1];
        int buf = 0;
        int have1 = 0;

        for (int tb = 1; tb < TT; tb += 4) {
            int needrow = tb + 7; if (needrow > 255) needrow = 255;
            if (needrow >= 128 && !have1) {
                while (ld_acq_gpu(f1p) == 0) __nanosleep(64);
                have1 = 1;
            }

            float enext[4];
#pragma unroll
            for (int i = 0; i < 4; i++) {
                int tt = tb + 4 + i;
                enext[i] = (tt < TT) ? emisb[(size_t)tt * KK + j] : 0.f;
            }
            float eexp[4];
#pragma unroll
            for (int i = 0; i < 4; i++) eexp[i] = __expf(ecur[i]);

#pragma unroll
            for (int i = 0; i < 4; i++) {
                const int t = tb + i;
                if (t >= TT) break;

                float p0 = s_P[buf][0];
                const u64t* P2 = (const u64t*)&s_P[buf][k0];
                u64t s0 = 0ull, s1 = 0ull, s2 = 0ull, s3 = 0ull;
#pragma unroll
                for (int m = 0; m < 4; m++) {
                    s0 = ffma2(P2[4 * m + 0], E2[4 * m + 0], s0);
                    s1 = ffma2(P2[4 * m + 1], E2[4 * m + 1], s1);
                    s2 = ffma2(P2[4 * m + 2], E2[4 * m + 2], s2);
                    s3 = ffma2(P2[4 * m + 3], E2[4 * m + 3], s3);
                }
                float l0, h0, l1, h1, l2, h2, l3, h3;
                unpack2(s0, &l0, &h0);
                unpack2(s1, &l1, &h1);
                unpack2(s2, &l2, &h2);
                unpack2(s3, &l3, &h3);
                float S = ((l0 + h0) + (l1 + h1)) + ((l2 + h2) + (l3 + h3));
                S += __shfl_xor_sync(0xFFFFFFFFu, S, 1);

                int e0i = (int)(__float_as_uint(p0) >> 23);
                float scale = __uint_as_float((unsigned)(254 - e0i) << 23);
                if (t < len) {
                    prevP = S * scale * eexp[i];
                    iexp += e0i - 127;
                }
                if (h == 0) s_P[buf ^ 1][j] = prevP;
                asm volatile("bar.sync 2, 128;" ::: "memory");
                buf ^= 1;
            }
#pragma unroll
            for (int i = 0; i < 4; i++) ecur[i] = enext[i];
        }

        float sp = (h == 0) ? prevP : 0.f;
#pragma unroll
        for (int o = 16; o; o >>= 1) sp += __shfl_xor_sync(0xFFFFFFFFu, sp, o);
        if ((ft & 31) == 0) s_red[ft >> 5] = sp;

        float uacc = 0.f;
#pragma unroll
        for (int i = 0; i < 2; i++) {
            int tt = ft + 128 * i;
            if (tt < len) {
                int tg = target[b * TT + tt];
                uacc += emisb[(size_t)tt * KK + tg];
                if (tt >= 1) uacc += trans_g[target[b * TT + tt - 1] * KK + tg];
            }
        }
#pragma unroll
        for (int o = 16; o; o >>= 1) uacc += __shfl_xor_sync(0xFFFFFFFFu, uacc, o);
        if ((ft & 31) == 0) s_red[4 + (ft >> 5)] = uacc;
        asm volatile("bar.sync 2, 128;" ::: "memory");

        if (ft == 0) {
            float sumP = s_red[0] + s_red[1] + s_red[2] + s_red[3];
            float score = s_red[4] + s_red[5] + s_red[6] + s_red[7];
            const float LN2 = 0.69314718055994531f;
            out_ll[b] = score - ((float)iexp * LN2 + logf(sumP));
        }
    }
}

// ---------------------------------------------------------------------------
extern "C" void kernel_launch(void* const* d_in, const int* in_sizes, int n_in,
                              void* d_out, int out_size) {
    const float* hidden = (const float*)d_in[0];
    const int*   masks  = (const int*)d_in[1];
    const int*   target = (const int*)d_in[2];
    const float* Wm     = (const float*)d_in[3];
    const float* bias   = (const float*)d_in[4];
    const float* trans  = (const float*)d_in[5];
    float* out = (float*)d_out;

    zero_flags_kernel<<<1, 2 * BB>>>();
    cudaFuncSetAttribute(fused2_kernel,
                         cudaFuncAttributeMaxDynamicSharedMemorySize, SMEM_BYTES);
    fused2_kernel<<<2 * BB, 256, SMEM_BYTES>>>(hidden, masks, target, Wm, bias,
                                               trans, out, out + (size_t)BB * TT);
}